// round 5
// baseline (speedup 1.0000x reference)
#include <cuda_runtime.h>

#define TPB     256
#define NLAYERS 5
#define H       32
#define E       32

typedef unsigned long long ull;

// ---- packed f32x2 helpers (sm_103a) ----
__device__ __forceinline__ ull pack2(float lo, float hi) {
    ull r; asm("mov.b64 %0, {%1, %2};" : "=l"(r) : "f"(lo), "f"(hi)); return r;
}
__device__ __forceinline__ void unpack2(ull v, float& lo, float& hi) {
    asm("mov.b64 {%0, %1}, %2;" : "=f"(lo), "=f"(hi) : "l"(v));
}
__device__ __forceinline__ ull fma2(ull a, ull b, ull c) {
    ull d; asm("fma.rn.f32x2 %0, %1, %2, %3;" : "=l"(d) : "l"(a), "l"(b), "l"(c)); return d;
}
__device__ __forceinline__ float rcpa(float x) {
    float r; asm("rcp.approx.f32 %0, %1;" : "=f"(r) : "f"(x)); return r;
}
__device__ __forceinline__ float ex2a(float x) {
    float r; asm("ex2.approx.f32 %0, %1;" : "=f"(r) : "f"(x)); return r;
}
__device__ __forceinline__ float sigm(float x) {           // 1/(1+2^(-x*log2e))
    return rcpa(1.0f + ex2a(-1.442695041f * x));
}
__device__ __forceinline__ float tanh_(float x) {          // 2*sigm(2x)-1
    return fmaf(2.0f, rcpa(1.0f + ex2a(-2.885390082f * x)), -1.0f);
}

// Shared memory layout (float units)
#define SM_W    0                    // 5*96*32 = 15360 (w_ih, natural layout)
#define SM_BR   (SM_W   + 15360)     // 160: b_ih+b_hh (r rows)
#define SM_BZ   (SM_BR  + 160)       // 160: b_ih+b_hh (z rows)
#define SM_BN   (SM_BZ  + 160)       // 160: b_ih (n rows)
#define SM_BHN  (SM_BN  + 160)       // 160: b_hh (n rows)
#define SM_FW   (SM_BHN + 160)       // 1024: fc_w
#define SM_FB   (SM_FW  + 1024)      // 32
#define SM_HB   (SM_FB  + 32)        // 1024 slots * 34 floats (8B-aligned rows, conflict-free)
#define SM_FLOATS (SM_HB + 1024*34)
#define SMEM_BYTES (SM_FLOATS * sizeof(float))   // 207,488 B

__global__ void __launch_bounds__(TPB, 1) gru4(
    const float* __restrict__ x,
    const float* __restrict__ w_ih,
    const float* __restrict__ b_ih,
    const float* __restrict__ b_hh,
    const float* __restrict__ fc_w,
    const float* __restrict__ fc_b,
    float* __restrict__ out)
{
    extern __shared__ float sm[];
    float* SW  = sm + SM_W;
    float* BR  = sm + SM_BR;
    float* BZ  = sm + SM_BZ;
    float* BN  = sm + SM_BN;
    float* BHN = sm + SM_BHN;
    float* FW  = sm + SM_FW;
    float* FB  = sm + SM_FB;
    float* HB  = sm + SM_HB;

    const int tid = threadIdx.x;

    // ---- cooperative preload (weights kept in natural packed layout) ----
    {
        const float4* src = (const float4*)w_ih;
        float4* dst = (float4*)SW;
        for (int i = tid; i < 15360 / 4; i += TPB) dst[i] = src[i];
    }
    for (int i = tid; i < NLAYERS * H; i += TPB) {
        int l = i >> 5, j = i & 31;
        BR[i]  = b_ih[l * 96 + j]      + b_hh[l * 96 + j];
        BZ[i]  = b_ih[l * 96 + 32 + j] + b_hh[l * 96 + 32 + j];
        BN[i]  = b_ih[l * 96 + 64 + j];
        BHN[i] = b_hh[l * 96 + 64 + j];
    }
    {
        const float4* src = (const float4*)fc_w;
        float4* dst = (float4*)FW;
        for (int i = tid; i < 1024 / 4; i += TPB) dst[i] = src[i];
    }
    if (tid < E) FB[tid] = fc_b[tid];
    __syncthreads();

    // ---- 4 batch elements per thread (interleaved by TPB: coalesced) ----
    const size_t base = (size_t)blockIdx.x * (4 * TPB) + tid;

    ull v[4][16];   // per element: 16 packed (x[2c], x[2c+1]) pairs
#pragma unroll
    for (int k = 0; k < 4; k++) {
        const ulonglong2* xp = (const ulonglong2*)(x + (base + (size_t)k * TPB) * E);
#pragma unroll
        for (int c = 0; c < 8; c++) {
            ulonglong2 t = xp[c];
            v[k][2 * c] = t.x; v[k][2 * c + 1] = t.y;
        }
    }

    // ---- 5 fused GRU layers (h0 = 0: w_hh path collapses to b_hh) ----
    for (int l = 0; l < NLAYERS; l++) {
        const float* SWl = SW + l * 3072;
        const float* brp  = BR  + l * H;
        const float* bzp  = BZ  + l * H;
        const float* bnp  = BN  + l * H;
        const float* bhnp = BHN + l * H;
#pragma unroll 2
        for (int j = 0; j < H; j++) {
            // gate rows are 32 floats each: r row j, z row 32+j, n row 64+j
            const ulonglong2* Wr = (const ulonglong2*)(SWl + (size_t)j * H);
            const ulonglong2* Wz = (const ulonglong2*)(SWl + (size_t)(32 + j) * H);
            const ulonglong2* Wn = (const ulonglong2*)(SWl + (size_t)(64 + j) * H);
            // biases folded into accumulator init: saves one FADD per gate per k
            const ull br2 = pack2(brp[j], 0.0f);
            const ull bz2 = pack2(bzp[j], 0.0f);
            const ull bn2 = pack2(bnp[j], 0.0f);
            const float bh = bhnp[j];
            ull ar[4], az[4], an[4];
#pragma unroll
            for (int k = 0; k < 4; k++) { ar[k] = br2; az[k] = bz2; an[k] = bn2; }
#pragma unroll
            for (int c = 0; c < 8; c++) {
                ulonglong2 wr = Wr[c];   // two packed weight pairs, no splat
                ulonglong2 wz = Wz[c];
                ulonglong2 wn = Wn[c];
#pragma unroll
                for (int k = 0; k < 4; k++) {
                    ar[k] = fma2(wr.x, v[k][2 * c], ar[k]);
                    ar[k] = fma2(wr.y, v[k][2 * c + 1], ar[k]);
                    az[k] = fma2(wz.x, v[k][2 * c], az[k]);
                    az[k] = fma2(wz.y, v[k][2 * c + 1], az[k]);
                    an[k] = fma2(wn.x, v[k][2 * c], an[k]);
                    an[k] = fma2(wn.y, v[k][2 * c + 1], an[k]);
                }
            }
#pragma unroll
            for (int k = 0; k < 4; k++) {
                float a0, a1;
                unpack2(ar[k], a0, a1); float r = sigm(a0 + a1);
                unpack2(az[k], a0, a1); float z = sigm(a0 + a1);
                unpack2(an[k], a0, a1); float n = tanh_(a0 + a1 + r * bh);
                HB[(tid + k * TPB) * 34 + j] = (1.0f - z) * n;
            }
        }
        // reload new hidden state as packed pairs (own slots: no barrier needed)
#pragma unroll
        for (int k = 0; k < 4; k++) {
            const ull* hp = (const ull*)(HB + (tid + k * TPB) * 34);
#pragma unroll
            for (int c = 0; c < 16; c++) v[k][c] = hp[c];
        }
    }

    // ---- FC epilogue: out = fc_w . h + fc_b, float4 stores ----
#pragma unroll 1
    for (int eg = 0; eg < 8; eg++) {
        float o[4][4];
#pragma unroll
        for (int t = 0; t < 4; t++) {
            const int e = eg * 4 + t;
            const ulonglong2* Fw = (const ulonglong2*)(FW + (size_t)e * H);
            const ull fb2 = pack2(FB[e], 0.0f);
            ull acc[4];
#pragma unroll
            for (int k = 0; k < 4; k++) acc[k] = fb2;
#pragma unroll
            for (int c = 0; c < 8; c++) {
                ulonglong2 w = Fw[c];
#pragma unroll
                for (int k = 0; k < 4; k++) {
                    acc[k] = fma2(w.x, v[k][2 * c], acc[k]);
                    acc[k] = fma2(w.y, v[k][2 * c + 1], acc[k]);
                }
            }
#pragma unroll
            for (int k = 0; k < 4; k++) {
                float a0, a1; unpack2(acc[k], a0, a1);
                o[k][t] = a0 + a1;
            }
        }
#pragma unroll
        for (int k = 0; k < 4; k++) {
            *(float4*)(out + (base + (size_t)k * TPB) * E + eg * 4) =
                make_float4(o[k][0], o[k][1], o[k][2], o[k][3]);
        }
    }
}

extern "C" void kernel_launch(void* const* d_in, const int* in_sizes, int n_in,
                              void* d_out, int out_size)
{
    const float* x    = (const float*)d_in[0];
    const float* w_ih = (const float*)d_in[1];
    // d_in[2] = w_hh: provably unused (h0 == 0 for every layer, T == 1)
    const float* b_ih = (const float*)d_in[3];
    const float* b_hh = (const float*)d_in[4];
    const float* fc_w = (const float*)d_in[5];
    const float* fc_b = (const float*)d_in[6];
    float* out = (float*)d_out;

    const int B = in_sizes[0] / E;                 // 1,048,576
    cudaFuncSetAttribute(gru4, cudaFuncAttributeMaxDynamicSharedMemorySize,
                         (int)SMEM_BYTES);
    const int grid = B / (4 * TPB);                // 1024 blocks, exact
    gru4<<<grid, TPB, SMEM_BYTES>>>(x, w_ih, b_ih, b_hh, fc_w, fc_b, out);
}